// round 9
// baseline (speedup 1.0000x reference)
#include <cuda_runtime.h>
#include <cuda_bf16.h>
#include <cstdint>

#define NROWS 100000
#define SDIM  1024
#define DDIM  512
#define NRBF  8
#define FEAT  20
#define GPITCH 21
#define NTHR  512

// dynamic smem layout (floats): C double buf 2*8192, x double buf 2*4096
#define SM_C_FLOATS 8192
#define SM_X_FLOATS 4096
#define DSMEM_BYTES ((2 * SM_C_FLOATS + 2 * SM_X_FLOATS) * 4)   // 98304

__device__ float g_G[FEAT * FEAT];
__device__ float g_H[FEAT];
__device__ float g_Wbar[FEAT];
__device__ float g_S[2];

__device__ __forceinline__ void cp16(void* dst, const void* src) {
    unsigned d = (unsigned)__cvta_generic_to_shared(dst);
    asm volatile("cp.async.cg.shared.global [%0], [%1], 16;" :: "r"(d), "l"(src));
}

// ============================================================
// K0: warp-per-item precompute (421 items)
// ============================================================
__global__ void k0_precompute(const float* __restrict__ W,
                              const float* __restrict__ b)
{
    const int lane = threadIdx.x & 31;
    const int item = (blockIdx.x * blockDim.x + threadIdx.x) >> 5;
    const float invD = 1.0f / DDIM;

    if (item < FEAT * FEAT) {
        const int l = item / FEAT, m = item % FEAT;
        const float4* wl = reinterpret_cast<const float4*>(W + l * DDIM);
        const float4* wm = reinterpret_cast<const float4*>(W + m * DDIM);
        float s = 0.f;
#pragma unroll
        for (int k = 0; k < 4; k++) {
            const float4 a = wl[lane + 32 * k];
            const float4 c = wm[lane + 32 * k];
            s = fmaf(a.x, c.x, fmaf(a.y, c.y, fmaf(a.z, c.z, fmaf(a.w, c.w, s))));
        }
#pragma unroll
        for (int o = 16; o; o >>= 1) s += __shfl_xor_sync(0xffffffffu, s, o);
        if (lane == 0) g_G[item] = s * invD;
    } else if (item < FEAT * FEAT + FEAT) {
        const int l = item - FEAT * FEAT;
        const float4* wl = reinterpret_cast<const float4*>(W + l * DDIM);
        const float4* bp = reinterpret_cast<const float4*>(b);
        float h = 0.f, wb = 0.f;
#pragma unroll
        for (int k = 0; k < 4; k++) {
            const float4 a = wl[lane + 32 * k];
            const float4 c = bp[lane + 32 * k];
            h  = fmaf(a.x, c.x, fmaf(a.y, c.y, fmaf(a.z, c.z, fmaf(a.w, c.w, h))));
            wb += (a.x + a.y) + (a.z + a.w);
        }
#pragma unroll
        for (int o = 16; o; o >>= 1) {
            h  += __shfl_xor_sync(0xffffffffu, h,  o);
            wb += __shfl_xor_sync(0xffffffffu, wb, o);
        }
        if (lane == 0) { g_H[l] = h * invD; g_Wbar[l] = wb * invD; }
    } else if (item == FEAT * FEAT + FEAT) {
        const float4* bp = reinterpret_cast<const float4*>(b);
        float bb = 0.f, b2 = 0.f;
#pragma unroll
        for (int k = 0; k < 4; k++) {
            const float4 c = bp[lane + 32 * k];
            bb += (c.x + c.y) + (c.z + c.w);
            b2  = fmaf(c.x, c.x, fmaf(c.y, c.y, fmaf(c.z, c.z, fmaf(c.w, c.w, b2))));
        }
#pragma unroll
        for (int o = 16; o; o >>= 1) {
            bb += __shfl_xor_sync(0xffffffffu, bb, o);
            b2 += __shfl_xor_sync(0xffffffffu, b2, o);
        }
        if (lane == 0) { g_S[0] = bb * invD; g_S[1] = b2 * invD; }
    }
}

// ============================================================
// Fused: R5 pipeline, 512 threads, 1 dim/thread, 2 blocks/SM
// ============================================================
__global__ __launch_bounds__(NTHR, 2)
void fused_kernel(const float* __restrict__ x,
                  const float* __restrict__ C,
                  const unsigned char* __restrict__ mask,
                  const float* __restrict__ W,
                  const float* __restrict__ bias,
                  const float* __restrict__ gamma,
                  const float* __restrict__ beta,
                  const float* __restrict__ gatep,
                  const float* __restrict__ centers,
                  const float* __restrict__ widths,
                  float* __restrict__ out)
{
    extern __shared__ float dsm[];
    float* sC = dsm;                          // [2][8192]
    float* sX = dsm + 2 * SM_C_FLOATS;        // [2][4096]

    const int tid  = threadIdx.x;
    const int lane = tid & 31;
    const int wid  = tid >> 5;
    const float gate = *gatep;

    __shared__ float sG[FEAT * GPITCH];
    __shared__ float sH[FEAT], sWb[FEAT], sS[2];
    __shared__ float sCW[2 * NRBF];
    __shared__ __align__(16) float zmu[8][24];

    for (int i = tid; i < FEAT * FEAT; i += NTHR)
        sG[(i / FEAT) * GPITCH + (i % FEAT)] = g_G[i];
    if (tid < FEAT)  { sH[tid] = g_H[tid]; sWb[tid] = g_Wbar[tid]; }
    if (tid < 2)       sS[tid] = g_S[tid];
    if (tid < NRBF)  { sCW[tid] = centers[tid]; sCW[NRBF + tid] = widths[tid]; }
    if (tid < 8)       zmu[tid][23] = 0.f;

    // register-resident weight column: one output dim per thread
    float w[FEAT];
#pragma unroll
    for (int f = 0; f < FEAT; f++) w[f] = W[f * DDIM + tid];
    const float bb = bias[tid];
    const float gg = gamma[tid];
    const float be = beta[tid];

    const int step = gridDim.x * 8;
    int base = blockIdx.x * 8;

    // ---- prologue: async-copy tile 0 (contiguous 8 rows) ----
    if (base < NROWS) {
        const float* gC = C + (size_t)base * SDIM;
        const float* gx = x + (size_t)base * DDIM;
#pragma unroll
        for (int k = 0; k < 4; k++) cp16(sC + (tid + NTHR * k) * 4, gC + (tid + NTHR * k) * 4);
#pragma unroll
        for (int k = 0; k < 2; k++) cp16(sX + (tid + NTHR * k) * 4, gx + (tid + NTHR * k) * 4);
        asm volatile("cp.async.commit_group;" ::: "memory");
    }

    int buf = 0;
    for (; base < NROWS; base += step, buf ^= 1) {
        const int nb = base + step;
        if (nb < NROWS) {
            float* dC = sC + (buf ^ 1) * SM_C_FLOATS;
            float* dX = sX + (buf ^ 1) * SM_X_FLOATS;
            const float* gC = C + (size_t)nb * SDIM;
            const float* gx = x + (size_t)nb * DDIM;
#pragma unroll
            for (int k = 0; k < 4; k++) cp16(dC + (tid + NTHR * k) * 4, gC + (tid + NTHR * k) * 4);
#pragma unroll
            for (int k = 0; k < 2; k++) cp16(dX + (tid + NTHR * k) * 4, gx + (tid + NTHR * k) * 4);
            asm volatile("cp.async.commit_group;" ::: "memory");
            asm volatile("cp.async.wait_group 1;" ::: "memory");
        } else {
            asm volatile("cp.async.wait_group 0;" ::: "memory");
        }
        __syncthreads();   // tile[buf] resident for all warps

        // ---- phase 1: warps 0..7, one row each; warps 8..15 go to barrier ----
        if (wid < 8) {
            const int myrow = base + wid;
            const float4* cp4 = reinterpret_cast<const float4*>(sC + buf * SM_C_FLOATS + wid * SDIM);
            float s = 0.f, s2 = 0.f, mn = 1e30f, mx = -1e30f;
#pragma unroll
            for (int h = 0; h < 2; h++) {
                float4 v[4];
#pragma unroll
                for (int k = 0; k < 4; k++) v[k] = cp4[lane + 32 * (4 * h + k)];
#pragma unroll
                for (int k = 0; k < 4; k++) {
                    const float a0 = fminf(fmaxf(v[k].x, 0.f), 1.f);
                    const float a1 = fminf(fmaxf(v[k].y, 0.f), 1.f);
                    const float a2 = fminf(fmaxf(v[k].z, 0.f), 1.f);
                    const float a3 = fminf(fmaxf(v[k].w, 0.f), 1.f);
                    s  += (a0 + a1) + (a2 + a3);
                    s2  = fmaf(a0, a0, fmaf(a1, a1, fmaf(a2, a2, fmaf(a3, a3, s2))));
                    mn  = fminf(mn, fminf(fminf(a0, a1), fminf(a2, a3)));
                    mx  = fmaxf(mx, fmaxf(fmaxf(a0, a1), fmaxf(a2, a3)));
                }
            }
#pragma unroll
            for (int o = 16; o; o >>= 1) {
                s  += __shfl_xor_sync(0xffffffffu, s,  o);
                s2 += __shfl_xor_sync(0xffffffffu, s2, o);
                mn  = fminf(mn, __shfl_xor_sync(0xffffffffu, mn, o));
                mx  = fmaxf(mx, __shfl_xor_sync(0xffffffffu, mx, o));
            }
            const float mean = s  * (1.f / SDIM);
            const float m2   = s2 * (1.f / SDIM);
            const float sd   = sqrtf(fmaxf(m2 - mean * mean, 0.f));

            float zl = 0.f;
            if (lane < FEAT) {
                if      (lane == 0) zl = mean;
                else if (lane == 1) zl = mx;
                else if (lane == 2) zl = mn;
                else if (lane == 3) zl = sd;
                else {
                    const float v0 = (lane < 4 + NRBF) ? mean : mx;
                    const int   ci = (lane < 4 + NRBF) ? (lane - 4) : (lane - 4 - NRBF);
                    const float dd = (v0 - sCW[ci]) / (sCW[NRBF + ci] + 1e-6f);
                    zl = __expf(-0.5f * dd * dd);
                }
                zmu[wid][lane] = zl;
            }
            __syncwarp();

            // analytic LN: mu = z.wbar + bbar ; E2 = z'Gz + 2 z.h + mean(b^2)
            float q = 0.f, m = 0.f;
            if (lane < FEAT) {
                float gz = 0.f;
#pragma unroll
                for (int j = 0; j < FEAT; j++)
                    gz = fmaf(sG[lane * GPITCH + j], zmu[wid][j], gz);
                q = zl * fmaf(2.f, sH[lane], gz);
                m = zl * sWb[lane];
            }
#pragma unroll
            for (int o = 16; o; o >>= 1) {
                q += __shfl_xor_sync(0xffffffffu, q, o);
                m += __shfl_xor_sync(0xffffffffu, m, o);
            }
            if (lane == 0) {
                const float mu  = m + sS[0];
                const float var = fmaxf(q + sS[1] - mu * mu, 0.f);
                const float g   = mask[myrow] ? 0.f : gate;
                zmu[wid][20] = mu;
                zmu[wid][21] = g * rsqrtf(var + 1e-5f);
                zmu[wid][22] = g;
            }
        }
        __syncthreads();   // A: all 8 rows ready

        // ---- phase 2: all 16 warps, 1 dim/thread over 8 rows ----
        const float* xb = sX + buf * SM_X_FLOATS;
#pragma unroll
        for (int r = 0; r < 8; r++) {
            float zr[24];
            const float4* sp = reinterpret_cast<const float4*>(zmu[r]);
#pragma unroll
            for (int k = 0; k < 6; k++) *reinterpret_cast<float4*>(zr + 4 * k) = sp[k];
            const float xx = xb[r * DDIM + tid];

            float p = bb;
#pragma unroll
            for (int f = 0; f < FEAT; f++) p = fmaf(zr[f], w[f], p);

            const float mu = zr[20], grs = zr[21], g = zr[22];
            out[(size_t)(base + r) * DDIM + tid] =
                fmaf(grs * gg, p - mu, fmaf(g, be, xx));
        }
        __syncthreads();   // B: buf + zmu safe to overwrite
    }
}

extern "C" void kernel_launch(void* const* d_in, const int* in_sizes, int n_in,
                              void* d_out, int out_size)
{
    const float*         x       = (const float*)d_in[0];
    const float*         C       = (const float*)d_in[1];
    const unsigned char* mask    = (const unsigned char*)d_in[2];
    const float*         W       = (const float*)d_in[3];
    const float*         bias    = (const float*)d_in[4];
    const float*         gamma   = (const float*)d_in[5];
    const float*         beta    = (const float*)d_in[6];
    const float*         gate    = (const float*)d_in[7];
    const float*         centers = (const float*)d_in[8];
    const float*         widths  = (const float*)d_in[9];
    float*               out     = (float*)d_out;

    static bool attr_set = false;
    if (!attr_set) {
        cudaFuncSetAttribute(fused_kernel,
                             cudaFuncAttributeMaxDynamicSharedMemorySize, DSMEM_BYTES);
        attr_set = true;
    }

    k0_precompute<<<53, 256>>>(W, bias);
    fused_kernel<<<296, NTHR, DSMEM_BYTES>>>(x, C, mask, W, bias, gamma, beta,
                                             gate, centers, widths, out);
}

// round 10
// speedup vs baseline: 1.2003x; 1.2003x over previous
#include <cuda_runtime.h>
#include <cuda_bf16.h>
#include <cstdint>

#define NROWS 100000
#define SDIM  1024
#define DDIM  512
#define NRBF  8
#define FEAT  20
#define GPITCH 21
#define NSTAGE 3

#define SM_C_FLOATS 8192                       // one 8-row C stage
#define DSMEM_BYTES (NSTAGE * SM_C_FLOATS * 4) // 98304

__device__ float g_G[FEAT * FEAT];
__device__ float g_H[FEAT];
__device__ float g_Wbar[FEAT];
__device__ float g_S[2];

__device__ __forceinline__ void cp16(void* dst, const void* src) {
    unsigned d = (unsigned)__cvta_generic_to_shared(dst);
    asm volatile("cp.async.cg.shared.global [%0], [%1], 16;" :: "r"(d), "l"(src));
}

// ============================================================
// K0: warp-per-item precompute (421 items)
// ============================================================
__global__ void k0_precompute(const float* __restrict__ W,
                              const float* __restrict__ b)
{
    const int lane = threadIdx.x & 31;
    const int item = (blockIdx.x * blockDim.x + threadIdx.x) >> 5;
    const float invD = 1.0f / DDIM;

    if (item < FEAT * FEAT) {
        const int l = item / FEAT, m = item % FEAT;
        const float4* wl = reinterpret_cast<const float4*>(W + l * DDIM);
        const float4* wm = reinterpret_cast<const float4*>(W + m * DDIM);
        float s = 0.f;
#pragma unroll
        for (int k = 0; k < 4; k++) {
            const float4 a = wl[lane + 32 * k];
            const float4 c = wm[lane + 32 * k];
            s = fmaf(a.x, c.x, fmaf(a.y, c.y, fmaf(a.z, c.z, fmaf(a.w, c.w, s))));
        }
#pragma unroll
        for (int o = 16; o; o >>= 1) s += __shfl_xor_sync(0xffffffffu, s, o);
        if (lane == 0) g_G[item] = s * invD;
    } else if (item < FEAT * FEAT + FEAT) {
        const int l = item - FEAT * FEAT;
        const float4* wl = reinterpret_cast<const float4*>(W + l * DDIM);
        const float4* bp = reinterpret_cast<const float4*>(b);
        float h = 0.f, wb = 0.f;
#pragma unroll
        for (int k = 0; k < 4; k++) {
            const float4 a = wl[lane + 32 * k];
            const float4 c = bp[lane + 32 * k];
            h  = fmaf(a.x, c.x, fmaf(a.y, c.y, fmaf(a.z, c.z, fmaf(a.w, c.w, h))));
            wb += (a.x + a.y) + (a.z + a.w);
        }
#pragma unroll
        for (int o = 16; o; o >>= 1) {
            h  += __shfl_xor_sync(0xffffffffu, h,  o);
            wb += __shfl_xor_sync(0xffffffffu, wb, o);
        }
        if (lane == 0) { g_H[l] = h * invD; g_Wbar[l] = wb * invD; }
    } else if (item == FEAT * FEAT + FEAT) {
        const float4* bp = reinterpret_cast<const float4*>(b);
        float bb = 0.f, b2 = 0.f;
#pragma unroll
        for (int k = 0; k < 4; k++) {
            const float4 c = bp[lane + 32 * k];
            bb += (c.x + c.y) + (c.z + c.w);
            b2  = fmaf(c.x, c.x, fmaf(c.y, c.y, fmaf(c.z, c.z, fmaf(c.w, c.w, b2))));
        }
#pragma unroll
        for (int o = 16; o; o >>= 1) {
            bb += __shfl_xor_sync(0xffffffffu, bb, o);
            b2 += __shfl_xor_sync(0xffffffffu, b2, o);
        }
        if (lane == 0) { g_S[0] = bb * invD; g_S[1] = b2 * invD; }
    }
}

// ============================================================
// Fused: 3-stage C ring + register-prefetched x, 8 rows/tile
// ============================================================
__global__ __launch_bounds__(256)
void fused_kernel(const float* __restrict__ x,
                  const float* __restrict__ C,
                  const unsigned char* __restrict__ mask,
                  const float* __restrict__ W,
                  const float* __restrict__ bias,
                  const float* __restrict__ gamma,
                  const float* __restrict__ beta,
                  const float* __restrict__ gatep,
                  const float* __restrict__ centers,
                  const float* __restrict__ widths,
                  float* __restrict__ out)
{
    extern __shared__ float sC[];              // [NSTAGE][8192]

    const int tid  = threadIdx.x;
    const int lane = tid & 31;
    const int wid  = tid >> 5;
    const int d0   = tid * 2;
    const float gate = *gatep;

    __shared__ float sG[FEAT * GPITCH];
    __shared__ float sH[FEAT], sWb[FEAT], sS[2];
    __shared__ float sCW[2 * NRBF];
    __shared__ __align__(16) float zmu[8][24];

    for (int i = tid; i < FEAT * FEAT; i += 256)
        sG[(i / FEAT) * GPITCH + (i % FEAT)] = g_G[i];
    if (tid < FEAT)  { sH[tid] = g_H[tid]; sWb[tid] = g_Wbar[tid]; }
    if (tid < 2)       sS[tid] = g_S[tid];
    if (tid < NRBF)  { sCW[tid] = centers[tid]; sCW[NRBF + tid] = widths[tid]; }
    if (tid < 8)       zmu[tid][23] = 0.f;

    float w[FEAT][2];
#pragma unroll
    for (int f = 0; f < FEAT; f++) {
        const float2 ww = *reinterpret_cast<const float2*>(W + f * DDIM + d0);
        w[f][0] = ww.x; w[f][1] = ww.y;
    }
    const float2 bb = *reinterpret_cast<const float2*>(bias  + d0);
    const float2 gg = *reinterpret_cast<const float2*>(gamma + d0);
    const float2 be = *reinterpret_cast<const float2*>(beta  + d0);

    const int ntiles = NROWS / 8;              // 12500
    const int tstep  = gridDim.x;

    // ---- prologue: C stages 0,1 in flight; x tile0 in registers ----
#pragma unroll
    for (int p = 0; p < 2; p++) {
        const int t = blockIdx.x + p * tstep;
        if (t < ntiles) {
            const float* gC = C + (size_t)t * 8 * SDIM;
            float* dC = sC + p * SM_C_FLOATS;
#pragma unroll
            for (int k = 0; k < 8; k++) cp16(dC + (tid + 256 * k) * 4, gC + (tid + 256 * k) * 4);
        }
        asm volatile("cp.async.commit_group;" ::: "memory");
    }
    float2 x2[8];
    if (blockIdx.x < ntiles) {
        const float* gx = x + (size_t)blockIdx.x * 8 * DDIM;
#pragma unroll
        for (int r = 0; r < 8; r++)
            x2[r] = *reinterpret_cast<const float2*>(gx + r * DDIM + d0);
    }

    int i = 0;
    for (int t = blockIdx.x; t < ntiles; t += tstep, i++) {
        // ---- issue C for tile t+2 into stage (i+2)%3; always commit ----
        const int t2 = t + 2 * tstep;
        if (t2 < ntiles) {
            const float* gC = C + (size_t)t2 * 8 * SDIM;
            float* dC = sC + ((i + 2) % NSTAGE) * SM_C_FLOATS;
#pragma unroll
            for (int k = 0; k < 8; k++) cp16(dC + (tid + 256 * k) * 4, gC + (tid + 256 * k) * 4);
        }
        asm volatile("cp.async.commit_group;" ::: "memory");
        asm volatile("cp.async.wait_group %0;" :: "n"(2) : "memory");
        __syncthreads();   // stage i%3 resident for all warps

        // ---- prefetch next tile's x into registers (covered by this tile) ----
        const int t1 = t + tstep;
        float2 x2n[8];
        if (t1 < ntiles) {
            const float* gx = x + (size_t)t1 * 8 * DDIM;
#pragma unroll
            for (int r = 0; r < 8; r++)
                x2n[r] = *reinterpret_cast<const float2*>(gx + r * DDIM + d0);
        }

        const int base = t * 8;
        const int myrow = base + wid;

        // ---- phase 1: warp-per-row stats from smem stage ----
        const float4* cp4 = reinterpret_cast<const float4*>(
            sC + (i % NSTAGE) * SM_C_FLOATS + wid * SDIM);
        float s = 0.f, s2 = 0.f, mn = 1e30f, mx = -1e30f;
#pragma unroll
        for (int h = 0; h < 2; h++) {
            float4 v[4];
#pragma unroll
            for (int k = 0; k < 4; k++) v[k] = cp4[lane + 32 * (4 * h + k)];
#pragma unroll
            for (int k = 0; k < 4; k++) {
                const float a0 = fminf(fmaxf(v[k].x, 0.f), 1.f);
                const float a1 = fminf(fmaxf(v[k].y, 0.f), 1.f);
                const float a2 = fminf(fmaxf(v[k].z, 0.f), 1.f);
                const float a3 = fminf(fmaxf(v[k].w, 0.f), 1.f);
                s  += (a0 + a1) + (a2 + a3);
                s2  = fmaf(a0, a0, fmaf(a1, a1, fmaf(a2, a2, fmaf(a3, a3, s2))));
                mn  = fminf(mn, fminf(fminf(a0, a1), fminf(a2, a3)));
                mx  = fmaxf(mx, fmaxf(fmaxf(a0, a1), fmaxf(a2, a3)));
            }
        }
#pragma unroll
        for (int o = 16; o; o >>= 1) {
            s  += __shfl_xor_sync(0xffffffffu, s,  o);
            s2 += __shfl_xor_sync(0xffffffffu, s2, o);
            mn  = fminf(mn, __shfl_xor_sync(0xffffffffu, mn, o));
            mx  = fmaxf(mx, __shfl_xor_sync(0xffffffffu, mx, o));
        }
        const float mean = s  * (1.f / SDIM);
        const float m2   = s2 * (1.f / SDIM);
        const float sd   = sqrtf(fmaxf(m2 - mean * mean, 0.f));

        float zl = 0.f;
        if (lane < FEAT) {
            if      (lane == 0) zl = mean;
            else if (lane == 1) zl = mx;
            else if (lane == 2) zl = mn;
            else if (lane == 3) zl = sd;
            else {
                const float v0 = (lane < 4 + NRBF) ? mean : mx;
                const int   ci = (lane < 4 + NRBF) ? (lane - 4) : (lane - 4 - NRBF);
                const float dd = (v0 - sCW[ci]) / (sCW[NRBF + ci] + 1e-6f);
                zl = __expf(-0.5f * dd * dd);
            }
            zmu[wid][lane] = zl;
        }
        __syncwarp();

        // ---- analytic LN: mu = z.wbar + bbar ; E2 = z'Gz + 2 z.h + mean(b^2) ----
        float q = 0.f, m = 0.f;
        if (lane < FEAT) {
            float gz = 0.f;
#pragma unroll
            for (int j = 0; j < FEAT; j++)
                gz = fmaf(sG[lane * GPITCH + j], zmu[wid][j], gz);
            q = zl * fmaf(2.f, sH[lane], gz);
            m = zl * sWb[lane];
        }
#pragma unroll
        for (int o = 16; o; o >>= 1) {
            q += __shfl_xor_sync(0xffffffffu, q, o);
            m += __shfl_xor_sync(0xffffffffu, m, o);
        }
        if (lane == 0) {
            const float mu  = m + sS[0];
            const float var = fmaxf(q + sS[1] - mu * mu, 0.f);
            const float g   = mask[myrow] ? 0.f : gate;
            zmu[wid][20] = mu;
            zmu[wid][21] = g * rsqrtf(var + 1e-5f);
            zmu[wid][22] = g;
        }
        __syncthreads();   // A: all 8 rows' z/mu ready

        // ---- phase 2: matvec + LN apply + residual (register x) ----
#pragma unroll
        for (int r = 0; r < 8; r++) {
            float zr[24];
            const float4* sp = reinterpret_cast<const float4*>(zmu[r]);
#pragma unroll
            for (int k = 0; k < 6; k++) *reinterpret_cast<float4*>(zr + 4 * k) = sp[k];

            float p0 = bb.x, p1 = bb.y;
#pragma unroll
            for (int f = 0; f < FEAT; f++) {
                p0 = fmaf(zr[f], w[f][0], p0);
                p1 = fmaf(zr[f], w[f][1], p1);
            }
            const float mu = zr[20], grs = zr[21], g = zr[22];
            const float o0 = fmaf(grs * gg.x, p0 - mu, fmaf(g, be.x, x2[r].x));
            const float o1 = fmaf(grs * gg.y, p1 - mu, fmaf(g, be.y, x2[r].y));
            *reinterpret_cast<float2*>(out + (size_t)(base + r) * DDIM + d0) =
                make_float2(o0, o1);
        }
        __syncthreads();   // B: stage + zmu safe for reuse

#pragma unroll
        for (int r = 0; r < 8; r++) x2[r] = x2n[r];
    }
}

extern "C" void kernel_launch(void* const* d_in, const int* in_sizes, int n_in,
                              void* d_out, int out_size)
{
    const float*         x       = (const float*)d_in[0];
    const float*         C       = (const float*)d_in[1];
    const unsigned char* mask    = (const unsigned char*)d_in[2];
    const float*         W       = (const float*)d_in[3];
    const float*         bias    = (const float*)d_in[4];
    const float*         gamma   = (const float*)d_in[5];
    const float*         beta    = (const float*)d_in[6];
    const float*         gate    = (const float*)d_in[7];
    const float*         centers = (const float*)d_in[8];
    const float*         widths  = (const float*)d_in[9];
    float*               out     = (float*)d_out;

    static bool attr_set = false;
    if (!attr_set) {
        cudaFuncSetAttribute(fused_kernel,
                             cudaFuncAttributeMaxDynamicSharedMemorySize, DSMEM_BYTES);
        attr_set = true;
    }

    k0_precompute<<<53, 256>>>(W, bias);
    fused_kernel<<<296, 256, DSMEM_BYTES>>>(x, C, mask, W, bias, gamma, beta,
                                            gate, centers, widths, out);
}

// round 11
// speedup vs baseline: 1.2628x; 1.0520x over previous
#include <cuda_runtime.h>
#include <cuda_bf16.h>
#include <cstdint>

#define NROWS 100000
#define SDIM  1024
#define DDIM  512
#define NRBF  8
#define FEAT  20
#define GPITCH 21
#define NSTAGE 3

#define SM_C_FLOATS 8192                       // one 8-row C stage
#define DSMEM_BYTES (NSTAGE * SM_C_FLOATS * 4) // 98304

__device__ float g_G[FEAT * FEAT];
__device__ float g_H[FEAT];
__device__ float g_Wbar[FEAT];
__device__ float g_S[2];

__device__ __forceinline__ void cp16(void* dst, const void* src) {
    unsigned d = (unsigned)__cvta_generic_to_shared(dst);
    asm volatile("cp.async.cg.shared.global [%0], [%1], 16;" :: "r"(d), "l"(src));
}

// ============================================================
// K0: warp-per-item precompute (421 items)
// ============================================================
__global__ void k0_precompute(const float* __restrict__ W,
                              const float* __restrict__ b)
{
    const int lane = threadIdx.x & 31;
    const int item = (blockIdx.x * blockDim.x + threadIdx.x) >> 5;
    const float invD = 1.0f / DDIM;

    if (item < FEAT * FEAT) {
        const int l = item / FEAT, m = item % FEAT;
        const float4* wl = reinterpret_cast<const float4*>(W + l * DDIM);
        const float4* wm = reinterpret_cast<const float4*>(W + m * DDIM);
        float s = 0.f;
#pragma unroll
        for (int k = 0; k < 4; k++) {
            const float4 a = wl[lane + 32 * k];
            const float4 c = wm[lane + 32 * k];
            s = fmaf(a.x, c.x, fmaf(a.y, c.y, fmaf(a.z, c.z, fmaf(a.w, c.w, s))));
        }
#pragma unroll
        for (int o = 16; o; o >>= 1) s += __shfl_xor_sync(0xffffffffu, s, o);
        if (lane == 0) g_G[item] = s * invD;
    } else if (item < FEAT * FEAT + FEAT) {
        const int l = item - FEAT * FEAT;
        const float4* wl = reinterpret_cast<const float4*>(W + l * DDIM);
        const float4* bp = reinterpret_cast<const float4*>(b);
        float h = 0.f, wb = 0.f;
#pragma unroll
        for (int k = 0; k < 4; k++) {
            const float4 a = wl[lane + 32 * k];
            const float4 c = bp[lane + 32 * k];
            h  = fmaf(a.x, c.x, fmaf(a.y, c.y, fmaf(a.z, c.z, fmaf(a.w, c.w, h))));
            wb += (a.x + a.y) + (a.z + a.w);
        }
#pragma unroll
        for (int o = 16; o; o >>= 1) {
            h  += __shfl_xor_sync(0xffffffffu, h,  o);
            wb += __shfl_xor_sync(0xffffffffu, wb, o);
        }
        if (lane == 0) { g_H[l] = h * invD; g_Wbar[l] = wb * invD; }
    } else if (item == FEAT * FEAT + FEAT) {
        const float4* bp = reinterpret_cast<const float4*>(b);
        float bb = 0.f, b2 = 0.f;
#pragma unroll
        for (int k = 0; k < 4; k++) {
            const float4 c = bp[lane + 32 * k];
            bb += (c.x + c.y) + (c.z + c.w);
            b2  = fmaf(c.x, c.x, fmaf(c.y, c.y, fmaf(c.z, c.z, fmaf(c.w, c.w, b2))));
        }
#pragma unroll
        for (int o = 16; o; o >>= 1) {
            bb += __shfl_xor_sync(0xffffffffu, bb, o);
            b2 += __shfl_xor_sync(0xffffffffu, b2, o);
        }
        if (lane == 0) { g_S[0] = bb * invD; g_S[1] = b2 * invD; }
    }
}

// ============================================================
// Fused, software-pipelined: apply(i-1) overlaps copy-wait(i)
// ============================================================
__global__ __launch_bounds__(256)
void fused_kernel(const float* __restrict__ x,
                  const float* __restrict__ C,
                  const unsigned char* __restrict__ mask,
                  const float* __restrict__ W,
                  const float* __restrict__ bias,
                  const float* __restrict__ gamma,
                  const float* __restrict__ beta,
                  const float* __restrict__ gatep,
                  const float* __restrict__ centers,
                  const float* __restrict__ widths,
                  float* __restrict__ out)
{
    extern __shared__ float sC[];              // [NSTAGE][8192]

    const int tid  = threadIdx.x;
    const int lane = tid & 31;
    const int wid  = tid >> 5;
    const int d0   = tid * 2;
    const float gate = *gatep;

    __shared__ float sG[FEAT * GPITCH];
    __shared__ float sH[FEAT], sWb[FEAT], sS[2];
    __shared__ float sCW[2 * NRBF];
    __shared__ __align__(16) float zmu[2][8][24];   // ping-pong stats buffers

    for (int i = tid; i < FEAT * FEAT; i += 256)
        sG[(i / FEAT) * GPITCH + (i % FEAT)] = g_G[i];
    if (tid < FEAT)  { sH[tid] = g_H[tid]; sWb[tid] = g_Wbar[tid]; }
    if (tid < 2)       sS[tid] = g_S[tid];
    if (tid < NRBF)  { sCW[tid] = centers[tid]; sCW[NRBF + tid] = widths[tid]; }
    if (tid < 16)      zmu[tid >> 3][tid & 7][23] = 0.f;

    float w[FEAT][2];
#pragma unroll
    for (int f = 0; f < FEAT; f++) {
        const float2 ww = *reinterpret_cast<const float2*>(W + f * DDIM + d0);
        w[f][0] = ww.x; w[f][1] = ww.y;
    }
    const float2 bb = *reinterpret_cast<const float2*>(bias  + d0);
    const float2 gg = *reinterpret_cast<const float2*>(gamma + d0);
    const float2 be = *reinterpret_cast<const float2*>(beta  + d0);

    const int ntiles = NROWS / 8;              // 12500
    const int tstep  = gridDim.x;

    // ---- prologue: C stages 0,1 in flight ----
#pragma unroll
    for (int p = 0; p < 2; p++) {
        const int t = blockIdx.x + p * tstep;
        if (t < ntiles) {
            const float* gC = C + (size_t)t * 8 * SDIM;
            float* dC = sC + p * SM_C_FLOATS;
#pragma unroll
            for (int k = 0; k < 8; k++) cp16(dC + (tid + 256 * k) * 4, gC + (tid + 256 * k) * 4);
        }
        asm volatile("cp.async.commit_group;" ::: "memory");
    }

    float2 xa[8], xb[8];                       // x for tile i-1 (consume) / i (landing)
    int lasti = 0;
    int lastt = -1;
    int i = 0;
    for (int t = blockIdx.x; t < ntiles; t += tstep, i++) {
        // ---- issue C for tile t+2; always commit ----
        const int t2 = t + 2 * tstep;
        if (t2 < ntiles) {
            const float* gC = C + (size_t)t2 * 8 * SDIM;
            float* dC = sC + ((i + 2) % NSTAGE) * SM_C_FLOATS;
#pragma unroll
            for (int k = 0; k < 8; k++) cp16(dC + (tid + 256 * k) * 4, gC + (tid + 256 * k) * 4);
        }
        asm volatile("cp.async.commit_group;" ::: "memory");

        // ---- issue x loads for tile t (consumed next iteration) ----
        {
            const float* gx = x + (size_t)t * 8 * DDIM;
#pragma unroll
            for (int r = 0; r < 8; r++)
                xb[r] = *reinterpret_cast<const float2*>(gx + r * DDIM + d0);
        }

        // ---- APPLY tile t-tstep (overlaps DMA of tile t) ----
        if (i > 0) {
            const int pbase = (t - tstep) * 8;
            const float (*zp)[24] = zmu[(i - 1) & 1];
#pragma unroll
            for (int r = 0; r < 8; r++) {
                float zr[24];
                const float4* sp = reinterpret_cast<const float4*>(zp[r]);
#pragma unroll
                for (int k = 0; k < 6; k++) *reinterpret_cast<float4*>(zr + 4 * k) = sp[k];

                float p0 = bb.x, p1 = bb.y;
#pragma unroll
                for (int f = 0; f < FEAT; f++) {
                    p0 = fmaf(zr[f], w[f][0], p0);
                    p1 = fmaf(zr[f], w[f][1], p1);
                }
                const float mu = zr[20], grs = zr[21], g = zr[22];
                const float o0 = fmaf(grs * gg.x, p0 - mu, fmaf(g, be.x, xa[r].x));
                const float o1 = fmaf(grs * gg.y, p1 - mu, fmaf(g, be.y, xa[r].y));
                *reinterpret_cast<float2*>(out + (size_t)(pbase + r) * DDIM + d0) =
                    make_float2(o0, o1);
            }
        }

        // ---- now wait for tile t's C data ----
        asm volatile("cp.async.wait_group %0;" :: "n"(2) : "memory");
        __syncthreads();   // stage i%3 resident; apply reads of zmu done

        // ---- STATS tile t -> zmu[i&1] ----
        const int myrow = t * 8 + wid;
        const float4* cp4 = reinterpret_cast<const float4*>(
            sC + (i % NSTAGE) * SM_C_FLOATS + wid * SDIM);
        float s = 0.f, s2 = 0.f, mn = 1e30f, mx = -1e30f;
#pragma unroll
        for (int h = 0; h < 2; h++) {
            float4 v[4];
#pragma unroll
            for (int k = 0; k < 4; k++) v[k] = cp4[lane + 32 * (4 * h + k)];
#pragma unroll
            for (int k = 0; k < 4; k++) {
                const float a0 = fminf(fmaxf(v[k].x, 0.f), 1.f);
                const float a1 = fminf(fmaxf(v[k].y, 0.f), 1.f);
                const float a2 = fminf(fmaxf(v[k].z, 0.f), 1.f);
                const float a3 = fminf(fmaxf(v[k].w, 0.f), 1.f);
                s  += (a0 + a1) + (a2 + a3);
                s2  = fmaf(a0, a0, fmaf(a1, a1, fmaf(a2, a2, fmaf(a3, a3, s2))));
                mn  = fminf(mn, fminf(fminf(a0, a1), fminf(a2, a3)));
                mx  = fmaxf(mx, fmaxf(fmaxf(a0, a1), fmaxf(a2, a3)));
            }
        }
#pragma unroll
        for (int o = 16; o; o >>= 1) {
            s  += __shfl_xor_sync(0xffffffffu, s,  o);
            s2 += __shfl_xor_sync(0xffffffffu, s2, o);
            mn  = fminf(mn, __shfl_xor_sync(0xffffffffu, mn, o));
            mx  = fmaxf(mx, __shfl_xor_sync(0xffffffffu, mx, o));
        }
        const float mean = s  * (1.f / SDIM);
        const float m2   = s2 * (1.f / SDIM);
        const float sd   = sqrtf(fmaxf(m2 - mean * mean, 0.f));

        float zl = 0.f;
        if (lane < FEAT) {
            if      (lane == 0) zl = mean;
            else if (lane == 1) zl = mx;
            else if (lane == 2) zl = mn;
            else if (lane == 3) zl = sd;
            else {
                const float v0 = (lane < 4 + NRBF) ? mean : mx;
                const int   ci = (lane < 4 + NRBF) ? (lane - 4) : (lane - 4 - NRBF);
                const float dd = (v0 - sCW[ci]) / (sCW[NRBF + ci] + 1e-6f);
                zl = __expf(-0.5f * dd * dd);
            }
            zmu[i & 1][wid][lane] = zl;
        }
        __syncwarp();

        // analytic LN: mu = z.wbar + bbar ; E2 = z'Gz + 2 z.h + mean(b^2)
        float q = 0.f, m = 0.f;
        if (lane < FEAT) {
            float gz = 0.f;
#pragma unroll
            for (int j = 0; j < FEAT; j++)
                gz = fmaf(sG[lane * GPITCH + j], zmu[i & 1][wid][j], gz);
            q = zl * fmaf(2.f, sH[lane], gz);
            m = zl * sWb[lane];
        }
#pragma unroll
        for (int o = 16; o; o >>= 1) {
            q += __shfl_xor_sync(0xffffffffu, q, o);
            m += __shfl_xor_sync(0xffffffffu, m, o);
        }
        if (lane == 0) {
            const float mu  = m + sS[0];
            const float var = fmaxf(q + sS[1] - mu * mu, 0.f);
            const float g   = mask[myrow] ? 0.f : gate;
            zmu[i & 1][wid][20] = mu;
            zmu[i & 1][wid][21] = g * rsqrtf(var + 1e-5f);
            zmu[i & 1][wid][22] = g;
        }
        __syncthreads();   // zmu[i&1] published for next iteration's apply

        // ---- rotate x buffers ----
#pragma unroll
        for (int r = 0; r < 8; r++) xa[r] = xb[r];
        lastt = t; lasti = i;
    }

    // ---- epilogue: apply the final tile ----
    if (lastt >= 0) {
        const int pbase = lastt * 8;
        const float (*zp)[24] = zmu[lasti & 1];
#pragma unroll
        for (int r = 0; r < 8; r++) {
            float zr[24];
            const float4* sp = reinterpret_cast<const float4*>(zp[r]);
#pragma unroll
            for (int k = 0; k < 6; k++) *reinterpret_cast<float4*>(zr + 4 * k) = sp[k];

            float p0 = bb.x, p1 = bb.y;
#pragma unroll
            for (int f = 0; f < FEAT; f++) {
                p0 = fmaf(zr[f], w[f][0], p0);
                p1 = fmaf(zr[f], w[f][1], p1);
            }
            const float mu = zr[20], grs = zr[21], g = zr[22];
            const float o0 = fmaf(grs * gg.x, p0 - mu, fmaf(g, be.x, xa[r].x));
            const float o1 = fmaf(grs * gg.y, p1 - mu, fmaf(g, be.y, xa[r].y));
            *reinterpret_cast<float2*>(out + (size_t)(pbase + r) * DDIM + d0) =
                make_float2(o0, o1);
        }
    }
}

extern "C" void kernel_launch(void* const* d_in, const int* in_sizes, int n_in,
                              void* d_out, int out_size)
{
    const float*         x       = (const float*)d_in[0];
    const float*         C       = (const float*)d_in[1];
    const unsigned char* mask    = (const unsigned char*)d_in[2];
    const float*         W       = (const float*)d_in[3];
    const float*         bias    = (const float*)d_in[4];
    const float*         gamma   = (const float*)d_in[5];
    const float*         beta    = (const float*)d_in[6];
    const float*         gate    = (const float*)d_in[7];
    const float*         centers = (const float*)d_in[8];
    const float*         widths  = (const float*)d_in[9];
    float*               out     = (float*)d_out;

    static bool attr_set = false;
    if (!attr_set) {
        cudaFuncSetAttribute(fused_kernel,
                             cudaFuncAttributeMaxDynamicSharedMemorySize, DSMEM_BYTES);
        attr_set = true;
    }

    k0_precompute<<<53, 256>>>(W, bias);
    fused_kernel<<<296, 256, DSMEM_BYTES>>>(x, C, mask, W, bias, gamma, beta,
                                            gate, centers, widths, out);
}